// round 1
// baseline (speedup 1.0000x reference)
#include <cuda_runtime.h>

// ---------------------------------------------------------------------------
// GIN forward on GB300 — round 0
// Pipeline per conv layer:
//   1) pull-aggregate via CSR:  m = h + sum_{j->i} h[j]      (L2-bound gather)
//   2) GEMM1: t = m @ W1 + b1, fused BN column sum/sumsq stats
//   3) bn_finalize: per-column scale/shift
//   4) GEMM2: h = relu( relu(a*t+b) @ W2 + b2 )              (BN+ReLU fused in A-load)
// CSR (by dst) built once per call: hist -> single-block scan -> scatter.
// Pool + head MLP fused in one kernel (batch is sorted -> binary search ranges).
// ---------------------------------------------------------------------------

#define NN      50000           // nodes
#define M_PAD   50048           // nodes padded to multiple of 64 (GEMM tile)
#define HD      256             // hidden dim
#define EMAX    800000          // edges
#define BN_EPS  1e-5f

// ------------------------- scratch (device globals) ------------------------
__device__ int   g_deg[NN];
__device__ int   g_cursor[NN];
__device__ int   g_rowptr[NN + 1];
__device__ int   g_adj[EMAX];
__device__ float g_m[(size_t)M_PAD * HD];   // aggregated input to MLP
__device__ float g_t[(size_t)M_PAD * HD];   // GEMM1 output (pre-BN)
__device__ float g_h[(size_t)M_PAD * HD];   // layer output features
__device__ float g_stats[3 * 2 * HD];       // per-layer [sum(256), sumsq(256)]
__device__ float g_bna[HD];                 // BN fused scale
__device__ float g_bnb[HD];                 // BN fused shift

// ------------------------------ zero init ----------------------------------
__global__ void zero_kernel() {
    int i = blockIdx.x * blockDim.x + threadIdx.x;
    if (i < NN) g_deg[i] = 0;
    if (i < 3 * 2 * HD) g_stats[i] = 0.f;
}

// ------------------------------ CSR build ----------------------------------
__global__ void hist_kernel(const int* __restrict__ ei, int E) {
    int i = blockIdx.x * blockDim.x + threadIdx.x;
    if (i < E) atomicAdd(&g_deg[ei[E + i]], 1);   // row 1 = dst
}

__global__ void scan_kernel(int n) {
    __shared__ int sbuf[1024];
    int tid = threadIdx.x;
    int offset = 0;
    for (int base = 0; base < n; base += 1024) {
        __syncthreads();
        int v = (base + tid < n) ? g_deg[base + tid] : 0;
        sbuf[tid] = v;
        __syncthreads();
        #pragma unroll
        for (int off = 1; off < 1024; off <<= 1) {
            int t = (tid >= off) ? sbuf[tid - off] : 0;
            __syncthreads();
            sbuf[tid] += t;
            __syncthreads();
        }
        int incl  = sbuf[tid];
        int total = sbuf[1023];
        if (base + tid < n) {
            int excl = offset + incl - v;
            g_rowptr[base + tid] = excl;
            g_cursor[base + tid] = excl;
        }
        offset += total;
    }
    if (tid == 0) g_rowptr[n] = offset;
}

__global__ void scatter_kernel(const int* __restrict__ ei, int E) {
    int i = blockIdx.x * blockDim.x + threadIdx.x;
    if (i < E) {
        int dst = ei[E + i];
        int pos = atomicAdd(&g_cursor[dst], 1);
        g_adj[pos] = ei[i];                       // row 0 = src
    }
}

// --------------------------- pull aggregation ------------------------------
// one warp per destination node; lane covers float4 chunks of the row.
// CV4 = C/4 (32 for C=128, 64 for C=256).  FIRST: read from param (x) else g_h.
template <int CV4, bool FIRST>
__global__ void __launch_bounds__(256) agg_kernel(const float* __restrict__ hin) {
    int w    = (blockIdx.x * blockDim.x + threadIdx.x) >> 5;
    int lane = threadIdx.x & 31;
    if (w >= M_PAD) return;

    float4*       m4 = reinterpret_cast<float4*>(g_m);
    const float*  h  = FIRST ? hin : (const float*)g_h;
    const float4* h4 = reinterpret_cast<const float4*>(h);

    if (w >= NN) {                                 // zero padding rows
        float4 z = make_float4(0.f, 0.f, 0.f, 0.f);
        m4[(size_t)w * CV4 + lane] = z;
        if (CV4 == 64) m4[(size_t)w * CV4 + 32 + lane] = z;
        return;
    }

    float4 acc0 = h4[(size_t)w * CV4 + lane];      // self term (1+eps)*x, eps=0
    float4 acc1 = make_float4(0.f, 0.f, 0.f, 0.f);
    if (CV4 == 64) acc1 = h4[(size_t)w * CV4 + 32 + lane];

    int s = g_rowptr[w], e = g_rowptr[w + 1];
    for (int j = s; j < e; j++) {
        int src = __ldg(&g_adj[j]);
        const float4* hp = h4 + (size_t)src * CV4;
        float4 v0 = __ldg(&hp[lane]);
        acc0.x += v0.x; acc0.y += v0.y; acc0.z += v0.z; acc0.w += v0.w;
        if (CV4 == 64) {
            float4 v1 = __ldg(&hp[32 + lane]);
            acc1.x += v1.x; acc1.y += v1.y; acc1.z += v1.z; acc1.w += v1.w;
        }
    }
    m4[(size_t)w * CV4 + lane] = acc0;
    if (CV4 == 64) m4[(size_t)w * CV4 + 32 + lane] = acc1;
}

// ------------------------------- GEMM --------------------------------------
// C[M_PAD, 256] = act(A[M_PAD, K]) @ B[K, 256] + bias
// P2=false: A=g_m (plain), C=g_t, accumulate BN stats (guarded to rows < Mreal)
// P2=true : A=g_t with fused  relu(bna*k + bnb)  on load, C=g_h, relu epilogue
// Tiling: BM=64, BN=64, BK=16, 256 threads, 4x4 microtile per thread.
template <int K, bool P2>
__global__ void __launch_bounds__(256) gemm_kernel(
    const float* __restrict__ B, const float* __restrict__ bias,
    int Mreal, int layer)
{
    __shared__ float As[16][68];
    __shared__ float Bs[16][68];

    const float* A = P2 ? (const float*)g_t : (const float*)g_m;
    float*       C = P2 ? g_h : g_t;

    const int tid = threadIdx.x;
    const int tx = tid & 15, ty = tid >> 4;
    const int rowBase = blockIdx.x * 64;
    const int colBase = blockIdx.y * 64;
    const int aRow = tid >> 2;                // 0..63
    const int aCol = (tid & 3) * 4;           // 0,4,8,12
    const int bRow = tid >> 4;                // 0..15
    const int bCol = (tid & 15) * 4;          // 0..60

    float acc[4][4];
    #pragma unroll
    for (int i = 0; i < 4; i++)
        #pragma unroll
        for (int j = 0; j < 4; j++) acc[i][j] = 0.f;

    const float* Aptr = A + (size_t)(rowBase + aRow) * K + aCol;

    for (int k0 = 0; k0 < K; k0 += 16) {
        float4 av = *reinterpret_cast<const float4*>(Aptr + k0);
        if (P2) {
            int kk = k0 + aCol;
            av.x = fmaxf(fmaf(g_bna[kk + 0], av.x, g_bnb[kk + 0]), 0.f);
            av.y = fmaxf(fmaf(g_bna[kk + 1], av.y, g_bnb[kk + 1]), 0.f);
            av.z = fmaxf(fmaf(g_bna[kk + 2], av.z, g_bnb[kk + 2]), 0.f);
            av.w = fmaxf(fmaf(g_bna[kk + 3], av.w, g_bnb[kk + 3]), 0.f);
        }
        As[aCol + 0][aRow] = av.x;
        As[aCol + 1][aRow] = av.y;
        As[aCol + 2][aRow] = av.z;
        As[aCol + 3][aRow] = av.w;

        float4 bv = *reinterpret_cast<const float4*>(
            B + (size_t)(k0 + bRow) * HD + colBase + bCol);
        *reinterpret_cast<float4*>(&Bs[bRow][bCol]) = bv;

        __syncthreads();
        #pragma unroll
        for (int k = 0; k < 16; k++) {
            float4 a = *reinterpret_cast<const float4*>(&As[k][ty * 4]);
            float4 b = *reinterpret_cast<const float4*>(&Bs[k][tx * 4]);
            float ar[4] = {a.x, a.y, a.z, a.w};
            float br[4] = {b.x, b.y, b.z, b.w};
            #pragma unroll
            for (int i = 0; i < 4; i++)
                #pragma unroll
                for (int j = 0; j < 4; j++)
                    acc[i][j] = fmaf(ar[i], br[j], acc[i][j]);
        }
        __syncthreads();
    }

    float bj[4];
    #pragma unroll
    for (int j = 0; j < 4; j++) bj[j] = bias[colBase + tx * 4 + j];

    float out[4][4];
    #pragma unroll
    for (int i = 0; i < 4; i++) {
        int row = rowBase + ty * 4 + i;
        float4 vo;
        float v0 = acc[i][0] + bj[0];
        float v1 = acc[i][1] + bj[1];
        float v2 = acc[i][2] + bj[2];
        float v3 = acc[i][3] + bj[3];
        if (P2) { v0 = fmaxf(v0, 0.f); v1 = fmaxf(v1, 0.f);
                  v2 = fmaxf(v2, 0.f); v3 = fmaxf(v3, 0.f); }
        out[i][0] = v0; out[i][1] = v1; out[i][2] = v2; out[i][3] = v3;
        vo.x = v0; vo.y = v1; vo.z = v2; vo.w = v3;
        *reinterpret_cast<float4*>(&C[(size_t)row * HD + colBase + tx * 4]) = vo;
    }

    if (!P2) {   // BN statistics: block-reduce column sum / sumsq
        __shared__ float rs[16][64];
        __shared__ float rq[16][64];
        float ps[4] = {0.f, 0.f, 0.f, 0.f};
        float pq[4] = {0.f, 0.f, 0.f, 0.f};
        #pragma unroll
        for (int i = 0; i < 4; i++) {
            int row = rowBase + ty * 4 + i;
            if (row < Mreal) {
                #pragma unroll
                for (int j = 0; j < 4; j++) {
                    float v = out[i][j];
                    ps[j] += v;
                    pq[j] += v * v;
                }
            }
        }
        #pragma unroll
        for (int j = 0; j < 4; j++) {
            rs[ty][tx * 4 + j] = ps[j];
            rq[ty][tx * 4 + j] = pq[j];
        }
        __syncthreads();
        if (tid < 64) {
            float s = 0.f, q = 0.f;
            #pragma unroll
            for (int t = 0; t < 16; t++) { s += rs[t][tid]; q += rq[t][tid]; }
            float* stats = &g_stats[layer * 2 * HD];
            atomicAdd(&stats[colBase + tid], s);
            atomicAdd(&stats[HD + colBase + tid], q);
        }
    }
}

// --------------------------- BN finalize -----------------------------------
__global__ void bn_finalize_kernel(const float* __restrict__ gamma,
                                   const float* __restrict__ beta,
                                   int n, int layer) {
    int c = threadIdx.x;
    const float* stats = &g_stats[layer * 2 * HD];
    float inv_n = 1.f / (float)n;
    float m   = stats[c] * inv_n;
    float var = fmaxf(stats[HD + c] * inv_n - m * m, 0.f);
    float a   = gamma[c] * rsqrtf(var + BN_EPS);
    g_bna[c] = a;
    g_bnb[c] = beta[c] - a * m;
}

// ------------------------ pool + head MLP ----------------------------------
// batch is sorted: block g binary-searches its node range, sums rows into
// smem, then runs the 256->256 relu MLP and the 256->OUT projection.
__global__ void __launch_bounds__(256) pool_head_kernel(
    const int* __restrict__ batch, int n,
    const float* __restrict__ W1, const float* __restrict__ b1,
    const float* __restrict__ W2, const float* __restrict__ b2,
    float* __restrict__ out, int OUTC)
{
    int g = blockIdx.x;
    int tid = threadIdx.x;
    __shared__ float acc[HD];
    __shared__ float hid[HD];

    int lo = 0, hi = n;
    while (lo < hi) { int mid = (lo + hi) >> 1; if (batch[mid] < g) lo = mid + 1; else hi = mid; }
    int s = lo;
    hi = n;
    while (lo < hi) { int mid = (lo + hi) >> 1; if (batch[mid] < g + 1) lo = mid + 1; else hi = mid; }
    int e = lo;

    float a = 0.f;
    for (int r = s; r < e; r++) a += g_h[(size_t)r * HD + tid];
    acc[tid] = a;
    __syncthreads();

    float v = b1[tid];
    #pragma unroll 8
    for (int k = 0; k < HD; k++) v = fmaf(acc[k], W1[k * HD + tid], v);
    hid[tid] = fmaxf(v, 0.f);
    __syncthreads();

    if (tid < OUTC) {
        float o = b2[tid];
        #pragma unroll 8
        for (int k = 0; k < HD; k++) o = fmaf(hid[k], W2[k * OUTC + tid], o);
        out[g * OUTC + tid] = o;
    }
}

// ------------------------------- launch ------------------------------------
extern "C" void kernel_launch(void* const* d_in, const int* in_sizes, int n_in,
                              void* d_out, int out_size) {
    const float* x      = (const float*)d_in[0];
    const int*   ei     = (const int*)  d_in[1];
    const int*   batch  = (const int*)  d_in[2];
    const float* c0_W1  = (const float*)d_in[4];
    const float* c0_b1  = (const float*)d_in[5];
    const float* c0_g   = (const float*)d_in[6];
    const float* c0_be  = (const float*)d_in[7];
    const float* c0_W2  = (const float*)d_in[8];
    const float* c0_b2  = (const float*)d_in[9];
    const float* cs_W1  = (const float*)d_in[10];
    const float* cs_b1  = (const float*)d_in[11];
    const float* cs_g   = (const float*)d_in[12];
    const float* cs_be  = (const float*)d_in[13];
    const float* cs_W2  = (const float*)d_in[14];
    const float* cs_b2  = (const float*)d_in[15];
    const float* mlp_W1 = (const float*)d_in[16];
    const float* mlp_b1 = (const float*)d_in[17];
    const float* mlp_W2 = (const float*)d_in[18];
    const float* mlp_b2 = (const float*)d_in[19];

    const int N    = in_sizes[2];       // 50000
    const int E    = in_sizes[1] / 2;   // 800000
    const int OUTC = 10;
    const int G    = out_size / OUTC;   // 500
    float* out = (float*)d_out;

    const int aggBlocks  = M_PAD / 8;            // 1 warp per node, 8 warps/block
    const dim3 gemmGrid(M_PAD / 64, HD / 64);    // 782 x 4

    // CSR build
    zero_kernel<<<(NN + 255) / 256, 256>>>();
    hist_kernel<<<(E + 255) / 256, 256>>>(ei, E);
    scan_kernel<<<1, 1024>>>(N);
    scatter_kernel<<<(E + 255) / 256, 256>>>(ei, E);

    // ---- conv layer 0 (C_IN=128) ----
    agg_kernel<32, true><<<aggBlocks, 256>>>(x);
    gemm_kernel<128, false><<<gemmGrid, 256>>>(c0_W1, c0_b1, N, 0);
    bn_finalize_kernel<<<1, HD>>>(c0_g, c0_be, N, 0);
    gemm_kernel<256, true><<<gemmGrid, 256>>>(c0_W2, c0_b2, N, 0);

    // ---- conv layers 1..2 ----
    for (int l = 0; l < 2; l++) {
        agg_kernel<64, false><<<aggBlocks, 256>>>(nullptr);
        gemm_kernel<256, false><<<gemmGrid, 256>>>(cs_W1 + (size_t)l * HD * HD,
                                                   cs_b1 + l * HD, N, l + 1);
        bn_finalize_kernel<<<1, HD>>>(cs_g + l * HD, cs_be + l * HD, N, l + 1);
        gemm_kernel<256, true><<<gemmGrid, 256>>>(cs_W2 + (size_t)l * HD * HD,
                                                  cs_b2 + l * HD, N, l + 1);
    }

    // ---- pool + head ----
    pool_head_kernel<<<G, 256>>>(batch, N, mlp_W1, mlp_b1, mlp_W2, mlp_b2,
                                 out, OUTC);
}

// round 4
// speedup vs baseline: 1.3594x; 1.3594x over previous
#include <cuda_runtime.h>
#include <cuda_bf16.h>
#include <cstdint>

// ---------------------------------------------------------------------------
// GIN forward on GB300 — round 3: mma.sync bf16 split-fp32 GEMMs
// Fix vs R2: B fragments use ldmatrix NON-trans (weights stored [n,k] row-
// major already match the mma.row.col B fragment layout; .trans was wrong).
//   agg (CSR pull, fp32 acc -> bf16 hi/lo)  ->  mma GEMM1 (t fp32)
//   -> bn_stats -> bn_finalize -> convert (BN+ReLU, re-split hi/lo)
//   -> mma GEMM2 (relu, h fp32) -> ... -> pool+head
// GEMM: D = Ahi@Bhi + Ahi@Blo + Alo@Bhi  (Markidis), fp32 accum.
// ---------------------------------------------------------------------------

#define NN      50000
#define M_PAD   50048            // 391 * 128
#define HD      256
#define EMAX    800000
#define BN_EPS  1e-5f

// ------------------------- scratch (device globals) ------------------------
__device__ int   g_deg[NN];
__device__ int   g_cursor[NN];
__device__ int   g_rowptr[NN + 1];
__device__ int   g_adj[EMAX];
__device__ __nv_bfloat16 g_mhi[(size_t)M_PAD * HD];
__device__ __nv_bfloat16 g_mlo[(size_t)M_PAD * HD];
__device__ float g_t[(size_t)M_PAD * HD];
__device__ float g_h[(size_t)M_PAD * HD];
__device__ __nv_bfloat16 g_wthi[6 * HD * HD];   // weights, [N rows, K] bf16 hi
__device__ __nv_bfloat16 g_wtlo[6 * HD * HD];   // bf16 lo
__device__ float g_stats[3 * 2 * HD];
__device__ float g_bna[HD];
__device__ float g_bnb[HD];

// ------------------------------ PTX helpers --------------------------------
__device__ __forceinline__ uint32_t smem_u32(const void* p) {
    uint32_t a;
    asm("{ .reg .u64 t; cvta.to.shared.u64 t, %1; cvt.u32.u64 %0, t; }"
        : "=r"(a) : "l"(p));
    return a;
}
#define CP_ASYNC16(dst, src) \
    asm volatile("cp.async.cg.shared.global [%0], [%1], 16;" \
                 :: "r"(dst), "l"(src) : "memory")
#define CP_COMMIT()  asm volatile("cp.async.commit_group;" ::: "memory")
#define CP_WAIT0()   asm volatile("cp.async.wait_group 0;" ::: "memory")

__device__ __forceinline__ void ldm_x4(uint32_t* r, uint32_t addr) {
    asm volatile("ldmatrix.sync.aligned.m8n8.x4.shared.b16 {%0,%1,%2,%3}, [%4];"
                 : "=r"(r[0]), "=r"(r[1]), "=r"(r[2]), "=r"(r[3]) : "r"(addr));
}
__device__ __forceinline__ void mma_bf16(float* d, const uint32_t* a,
                                         const uint32_t* b) {
    asm volatile(
        "mma.sync.aligned.m16n8k16.row.col.f32.bf16.bf16.f32 "
        "{%0,%1,%2,%3}, {%4,%5,%6,%7}, {%8,%9}, {%0,%1,%2,%3};"
        : "+f"(d[0]), "+f"(d[1]), "+f"(d[2]), "+f"(d[3])
        : "r"(a[0]), "r"(a[1]), "r"(a[2]), "r"(a[3]), "r"(b[0]), "r"(b[1]));
}

// ------------------------------ zero init ----------------------------------
__global__ void zero_kernel() {
    int i = blockIdx.x * blockDim.x + threadIdx.x;
    if (i < NN) g_deg[i] = 0;
    if (i < 3 * 2 * HD) g_stats[i] = 0.f;
}

// ------------------------------ CSR build ----------------------------------
__global__ void hist_kernel(const int* __restrict__ ei, int E) {
    int i = blockIdx.x * blockDim.x + threadIdx.x;
    if (i < E) atomicAdd(&g_deg[ei[E + i]], 1);
}

__global__ void scan_kernel(int n) {
    __shared__ int sbuf[1024];
    int tid = threadIdx.x;
    int offset = 0;
    for (int base = 0; base < n; base += 1024) {
        __syncthreads();
        int v = (base + tid < n) ? g_deg[base + tid] : 0;
        sbuf[tid] = v;
        __syncthreads();
        #pragma unroll
        for (int off = 1; off < 1024; off <<= 1) {
            int t = (tid >= off) ? sbuf[tid - off] : 0;
            __syncthreads();
            sbuf[tid] += t;
            __syncthreads();
        }
        int incl  = sbuf[tid];
        int total = sbuf[1023];
        if (base + tid < n) {
            int excl = offset + incl - v;
            g_rowptr[base + tid] = excl;
            g_cursor[base + tid] = excl;
        }
        offset += total;
    }
    if (tid == 0) g_rowptr[n] = offset;
}

__global__ void scatter_kernel(const int* __restrict__ ei, int E) {
    int i = blockIdx.x * blockDim.x + threadIdx.x;
    if (i < E) {
        int dst = ei[E + i];
        int pos = atomicAdd(&g_cursor[dst], 1);
        g_adj[pos] = ei[i];
    }
}

// ------------------------------ splitting ----------------------------------
__device__ __forceinline__ void split_store4(size_t off, float4 v) {
    __nv_bfloat16 h0 = __float2bfloat16(v.x);
    __nv_bfloat16 h1 = __float2bfloat16(v.y);
    __nv_bfloat16 h2 = __float2bfloat16(v.z);
    __nv_bfloat16 h3 = __float2bfloat16(v.w);
    __nv_bfloat16 l0 = __float2bfloat16(v.x - __bfloat162float(h0));
    __nv_bfloat16 l1 = __float2bfloat16(v.y - __bfloat162float(h1));
    __nv_bfloat16 l2 = __float2bfloat16(v.z - __bfloat162float(h2));
    __nv_bfloat16 l3 = __float2bfloat16(v.w - __bfloat162float(h3));
    __nv_bfloat162* hp = reinterpret_cast<__nv_bfloat162*>(&g_mhi[off]);
    __nv_bfloat162* lp = reinterpret_cast<__nv_bfloat162*>(&g_mlo[off]);
    hp[0] = __halves2bfloat162(h0, h1);
    hp[1] = __halves2bfloat162(h2, h3);
    lp[0] = __halves2bfloat162(l0, l1);
    lp[1] = __halves2bfloat162(l2, l3);
}

// --------------------------- pull aggregation ------------------------------
template <int CV4, bool FIRST>
__global__ void __launch_bounds__(256) agg_kernel(const float* __restrict__ hin) {
    constexpr int K = CV4 * 4;
    int w    = (blockIdx.x * blockDim.x + threadIdx.x) >> 5;
    int lane = threadIdx.x & 31;
    if (w >= M_PAD) return;

    size_t off0 = (size_t)w * K + lane * 4;

    if (w >= NN) {
        float4 z = make_float4(0.f, 0.f, 0.f, 0.f);
        split_store4(off0, z);
        if (CV4 == 64) split_store4(off0 + 128, z);
        return;
    }

    const float*  h  = FIRST ? hin : (const float*)g_h;
    const float4* h4 = reinterpret_cast<const float4*>(h);

    float4 acc0 = h4[(size_t)w * CV4 + lane];
    float4 acc1 = make_float4(0.f, 0.f, 0.f, 0.f);
    if (CV4 == 64) acc1 = h4[(size_t)w * CV4 + 32 + lane];

    int s = g_rowptr[w], e = g_rowptr[w + 1];
    for (int j = s; j < e; j++) {
        int src = __ldg(&g_adj[j]);
        const float4* hp = h4 + (size_t)src * CV4;
        float4 v0 = __ldg(&hp[lane]);
        acc0.x += v0.x; acc0.y += v0.y; acc0.z += v0.z; acc0.w += v0.w;
        if (CV4 == 64) {
            float4 v1 = __ldg(&hp[32 + lane]);
            acc1.x += v1.x; acc1.y += v1.y; acc1.z += v1.z; acc1.w += v1.w;
        }
    }
    split_store4(off0, acc0);
    if (CV4 == 64) split_store4(off0 + 128, acc1);
}

// --------------------------- weight prep -----------------------------------
// src [K, 256] fp32 row-major -> slot: [256 rows, K] bf16 hi/lo (K-major)
__global__ void wprep_kernel(const float* __restrict__ src, int slot, int K) {
    int idx = blockIdx.x * blockDim.x + threadIdx.x;
    if (idx >= K * HD) return;
    int k = idx / HD, n = idx % HD;
    float v = src[idx];
    __nv_bfloat16 hi = __float2bfloat16(v);
    float r = v - __bfloat162float(hi);
    size_t o = (size_t)slot * HD * HD + (size_t)n * K + k;
    g_wthi[o] = hi;
    g_wtlo[o] = __float2bfloat16(r);
}

// -------------------------- mma.sync GEMM ----------------------------------
// C[M_PAD,256] = A @ W (+bias)(relu if P2). BM=128, BN=128, BK=32, 256 thr.
// SMEM rows padded to 80B (5x16B units) -> conflict-free ldmatrix.
// Stage buffer per array = 128 * 80 = 10240B; 4 arrays x 2 stages = 80KB.
#define ROWB   80
#define STG    10240
#define S_AHI  0
#define S_ALO  (2 * STG)
#define S_BHI  (4 * STG)
#define S_BLO  (6 * STG)
#define S_TOT  (8 * STG)

template <int K, bool P2>
__global__ void __launch_bounds__(256) gemm_mma(int wslot,
                                               const float* __restrict__ bias) {
    constexpr int CHUNKS = K / 32;
    extern __shared__ char smem[];
    const uint32_t sb = smem_u32(smem);

    const int tid  = threadIdx.x;
    const int wid  = tid >> 5;
    const int lane = tid & 31;
    const int rowBase = blockIdx.x * 128;
    const int colBase = blockIdx.y * 128;
    const int wm = (wid >> 1) * 32;          // warp m offset (0..96)
    const int wn = (wid & 1) * 64;           // warp n offset (0/64)

    const __nv_bfloat16* Whi = g_wthi + (size_t)wslot * HD * HD;
    const __nv_bfloat16* Wlo = g_wtlo + (size_t)wslot * HD * HD;
    float* C = P2 ? g_h : g_t;

    auto prefetch = [&](int c, int stage) {
        const uint32_t so = stage * STG;
        #pragma unroll
        for (int i = 0; i < 2; i++) {
            int u  = tid * 2 + i;
            int r  = u >> 2, c8 = u & 3;
            uint32_t sof = so + r * ROWB + c8 * 16;
            size_t ga = (size_t)(rowBase + r) * K + c * 32 + c8 * 8;
            CP_ASYNC16(sb + S_AHI + sof, (const void*)&g_mhi[ga]);
            CP_ASYNC16(sb + S_ALO + sof, (const void*)&g_mlo[ga]);
            size_t gb = (size_t)(colBase + r) * K + c * 32 + c8 * 8;
            CP_ASYNC16(sb + S_BHI + sof, (const void*)&Whi[gb]);
            CP_ASYNC16(sb + S_BLO + sof, (const void*)&Wlo[gb]);
        }
        CP_COMMIT();
    };

    float acc[2][8][4];
    #pragma unroll
    for (int mt = 0; mt < 2; mt++)
        #pragma unroll
        for (int nt = 0; nt < 8; nt++)
            #pragma unroll
            for (int j = 0; j < 4; j++) acc[mt][nt][j] = 0.f;

    // ldmatrix lane address mapping
    // A (rows m, cols k): m0=rows0-7/k0-7, m1=rows8-15/k0-7, m2=rows0-7/k8-15, m3=rows8-15/k8-15
    const int arow = (lane & 7) + ((lane >> 3) & 1) * 8;   // 0..15
    const int akh  = (lane >> 4) * 8;                      // 0 or 8 (k half)
    // B stored [n, k] row-major; NON-trans ldmatrix gives mma.col B fragment.
    // m0=n0-7/k0-7 (->b0 grp0), m1=n0-7/k8-15 (->b1 grp0), m2/m3 = n8-15.
    const int brow = (lane & 7) + ((lane >> 4) & 1) * 8;   // 0..15 (n)
    const int bkh  = ((lane >> 3) & 1) * 8;                // 0 or 8 (k half)

    prefetch(0, 0);

    for (int c = 0; c < CHUNKS; c++) {
        CP_WAIT0();
        __syncthreads();
        if (c + 1 < CHUNKS) prefetch(c + 1, (c + 1) & 1);

        const uint32_t so = (c & 1) * STG;
        #pragma unroll
        for (int kk = 0; kk < 32; kk += 16) {
            uint32_t ah[2][4], al[2][4];
            #pragma unroll
            for (int mt = 0; mt < 2; mt++) {
                uint32_t ad = sb + so + (wm + mt * 16 + arow) * ROWB
                            + (kk + akh) * 2;
                ldm_x4(ah[mt], S_AHI + ad);
                ldm_x4(al[mt], S_ALO + ad);
            }
            uint32_t bh[8][2], bl[8][2];
            #pragma unroll
            for (int np = 0; np < 4; np++) {
                uint32_t bd = sb + so + (wn + np * 16 + brow) * ROWB
                            + (kk + bkh) * 2;
                uint32_t th[4], tl[4];
                ldm_x4(th, S_BHI + bd);          // non-trans (fix)
                ldm_x4(tl, S_BLO + bd);          // non-trans (fix)
                bh[np*2][0] = th[0]; bh[np*2][1] = th[1];
                bh[np*2+1][0] = th[2]; bh[np*2+1][1] = th[3];
                bl[np*2][0] = tl[0]; bl[np*2][1] = tl[1];
                bl[np*2+1][0] = tl[2]; bl[np*2+1][1] = tl[3];
            }
            #pragma unroll
            for (int mt = 0; mt < 2; mt++)
                #pragma unroll
                for (int nt = 0; nt < 8; nt++) {
                    mma_bf16(acc[mt][nt], ah[mt], bh[nt]);
                    mma_bf16(acc[mt][nt], ah[mt], bl[nt]);
                    mma_bf16(acc[mt][nt], al[mt], bh[nt]);
                }
        }
        __syncthreads();
    }

    // epilogue: d0,d1 -> (row, col..col+1); d2,d3 -> (row+8, ...)
    const int erow = rowBase + wm + (lane >> 2);
    const int ecol0 = colBase + wn + (lane & 3) * 2;
    #pragma unroll
    for (int mt = 0; mt < 2; mt++) {
        #pragma unroll
        for (int nt = 0; nt < 8; nt++) {
            int col = ecol0 + nt * 8;
            float b0 = __ldg(bias + col), b1 = __ldg(bias + col + 1);
            float v0 = acc[mt][nt][0] + b0;
            float v1 = acc[mt][nt][1] + b1;
            float v2 = acc[mt][nt][2] + b0;
            float v3 = acc[mt][nt][3] + b1;
            if (P2) {
                v0 = fmaxf(v0, 0.f); v1 = fmaxf(v1, 0.f);
                v2 = fmaxf(v2, 0.f); v3 = fmaxf(v3, 0.f);
            }
            int r0 = erow + mt * 16;
            *reinterpret_cast<float2*>(&C[(size_t)r0 * HD + col])
                = make_float2(v0, v1);
            *reinterpret_cast<float2*>(&C[(size_t)(r0 + 8) * HD + col])
                = make_float2(v2, v3);
        }
    }
}

// ---------------------------- BN stats -------------------------------------
__global__ void bn_stats_kernel(int layer, int n) {
    int col = threadIdx.x;
    float s = 0.f, q = 0.f;
    for (int r = blockIdx.x; r < n; r += gridDim.x) {
        float v = g_t[(size_t)r * HD + col];
        s += v; q += v * v;
    }
    float* st = &g_stats[layer * 2 * HD];
    atomicAdd(&st[col], s);
    atomicAdd(&st[HD + col], q);
}

__global__ void bn_finalize_kernel(const float* __restrict__ gamma,
                                   const float* __restrict__ beta,
                                   int n, int layer) {
    int c = threadIdx.x;
    const float* stats = &g_stats[layer * 2 * HD];
    float inv_n = 1.f / (float)n;
    float m   = stats[c] * inv_n;
    float var = fmaxf(stats[HD + c] * inv_n - m * m, 0.f);
    float a   = gamma[c] * rsqrtf(var + BN_EPS);
    g_bna[c] = a;
    g_bnb[c] = beta[c] - a * m;
}

// ------------------- BN affine + ReLU + re-split ---------------------------
__global__ void __launch_bounds__(256) convert_kernel() {
    size_t i = ((size_t)blockIdx.x * blockDim.x + threadIdx.x) * 4;
    if (i >= (size_t)M_PAD * HD) return;
    int col = (int)(i & (HD - 1));
    float4 v = *reinterpret_cast<const float4*>(&g_t[i]);
    v.x = fmaxf(fmaf(g_bna[col + 0], v.x, g_bnb[col + 0]), 0.f);
    v.y = fmaxf(fmaf(g_bna[col + 1], v.y, g_bnb[col + 1]), 0.f);
    v.z = fmaxf(fmaf(g_bna[col + 2], v.z, g_bnb[col + 2]), 0.f);
    v.w = fmaxf(fmaf(g_bna[col + 3], v.w, g_bnb[col + 3]), 0.f);
    split_store4(i, v);
}

// ------------------------ pool + head MLP ----------------------------------
__global__ void __launch_bounds__(256) pool_head_kernel(
    const int* __restrict__ batch, int n,
    const float* __restrict__ W1, const float* __restrict__ b1,
    const float* __restrict__ W2, const float* __restrict__ b2,
    float* __restrict__ out, int OUTC)
{
    int g = blockIdx.x;
    int tid = threadIdx.x;
    __shared__ float acc[HD];
    __shared__ float hid[HD];

    int lo = 0, hi = n;
    while (lo < hi) { int mid = (lo + hi) >> 1; if (batch[mid] < g) lo = mid + 1; else hi = mid; }
    int s = lo;
    hi = n;
    while (lo < hi) { int mid = (lo + hi) >> 1; if (batch[mid] < g + 1) lo = mid + 1; else hi = mid; }
    int e = lo;

    float a = 0.f;
    for (int r = s; r < e; r++) a += g_h[(size_t)r * HD + tid];
    acc[tid] = a;
    __syncthreads();

    float v = b1[tid];
    #pragma unroll 8
    for (int k = 0; k < HD; k++) v = fmaf(acc[k], W1[k * HD + tid], v);
    hid[tid] = fmaxf(v, 0.f);
    __syncthreads();

    if (tid < OUTC) {
        float o = b2[tid];
        #pragma unroll 8
        for (int k = 0; k < HD; k++) o = fmaf(hid[k], W2[k * OUTC + tid], o);
        out[g * OUTC + tid] = o;
    }
}

// ------------------------------- launch ------------------------------------
extern "C" void kernel_launch(void* const* d_in, const int* in_sizes, int n_in,
                              void* d_out, int out_size) {
    const float* x      = (const float*)d_in[0];
    const int*   ei     = (const int*)  d_in[1];
    const int*   batch  = (const int*)  d_in[2];
    const float* c0_W1  = (const float*)d_in[4];
    const float* c0_b1  = (const float*)d_in[5];
    const float* c0_g   = (const float*)d_in[6];
    const float* c0_be  = (const float*)d_in[7];
    const float* c0_W2  = (const float*)d_in[8];
    const float* c0_b2  = (const float*)d_in[9];
    const float* cs_W1  = (const float*)d_in[10];
    const float* cs_b1  = (const float*)d_in[11];
    const float* cs_g   = (const float*)d_in[12];
    const float* cs_be  = (const float*)d_in[13];
    const float* cs_W2  = (const float*)d_in[14];
    const float* cs_b2  = (const float*)d_in[15];
    const float* mlp_W1 = (const float*)d_in[16];
    const float* mlp_b1 = (const float*)d_in[17];
    const float* mlp_W2 = (const float*)d_in[18];
    const float* mlp_b2 = (const float*)d_in[19];

    const int N    = in_sizes[2];
    const int E    = in_sizes[1] / 2;
    const int OUTC = 10;
    const int G    = out_size / OUTC;
    float* out = (float*)d_out;

    cudaFuncSetAttribute(gemm_mma<128, false>,
                         cudaFuncAttributeMaxDynamicSharedMemorySize, S_TOT);
    cudaFuncSetAttribute(gemm_mma<256, false>,
                         cudaFuncAttributeMaxDynamicSharedMemorySize, S_TOT);
    cudaFuncSetAttribute(gemm_mma<256, true>,
                         cudaFuncAttributeMaxDynamicSharedMemorySize, S_TOT);

    const int aggBlocks = M_PAD / 8;
    const dim3 gemmGrid(M_PAD / 128, 2);   // 391 x 2

    // CSR build
    zero_kernel<<<(NN + 255) / 256, 256>>>();
    hist_kernel<<<(E + 255) / 256, 256>>>(ei, E);
    scan_kernel<<<1, 1024>>>(N);
    scatter_kernel<<<(E + 255) / 256, 256>>>(ei, E);

    // weight prep (bf16 hi/lo, transposed to [N,K])
    wprep_kernel<<<(128 * HD + 255) / 256, 256>>>(c0_W1, 0, 128);
    wprep_kernel<<<(HD * HD + 255) / 256, 256>>>(c0_W2, 1, 256);
    wprep_kernel<<<(HD * HD + 255) / 256, 256>>>(cs_W1, 2, 256);
    wprep_kernel<<<(HD * HD + 255) / 256, 256>>>(cs_W2, 3, 256);
    wprep_kernel<<<(HD * HD + 255) / 256, 256>>>(cs_W1 + (size_t)HD * HD, 4, 256);
    wprep_kernel<<<(HD * HD + 255) / 256, 256>>>(cs_W2 + (size_t)HD * HD, 5, 256);

    const int convBlocks = (M_PAD * HD / 4 + 255) / 256;

    // ---- conv layer 0 (C_IN=128) ----
    agg_kernel<32, true><<<aggBlocks, 256>>>(x);
    gemm_mma<128, false><<<gemmGrid, 256, S_TOT>>>(0, c0_b1);
    bn_stats_kernel<<<256, HD>>>(0, N);
    bn_finalize_kernel<<<1, HD>>>(c0_g, c0_be, N, 0);
    convert_kernel<<<convBlocks, 256>>>();
    gemm_mma<256, true><<<gemmGrid, 256, S_TOT>>>(1, c0_b2);

    // ---- conv layers 1..2 ----
    for (int l = 0; l < 2; l++) {
        agg_kernel<64, false><<<aggBlocks, 256>>>(nullptr);
        gemm_mma<256, false><<<gemmGrid, 256, S_TOT>>>(2 + l * 2, cs_b1 + l * HD);
        bn_stats_kernel<<<256, HD>>>(l + 1, N);
        bn_finalize_kernel<<<1, HD>>>(cs_g + l * HD, cs_be + l * HD, N, l + 1);
        convert_kernel<<<convBlocks, 256>>>();
        gemm_mma<256, true><<<gemmGrid, 256, S_TOT>>>(3 + l * 2, cs_b2 + l * HD);
    }

    // ---- pool + head ----
    pool_head_kernel<<<G, 256>>>(batch, N, mlp_W1, mlp_b1, mlp_W2, mlp_b2,
                                 out, OUTC);
}